// round 5
// baseline (speedup 1.0000x reference)
#include <cuda_runtime.h>

#define SS   512
#define OUTN 12
#define BT   16           // batch per CTA
#define CTAS 128
#define NTHR 128
#define HS   20           // padded h row stride (floats)
#define XCH  64           // x staging chunk (timesteps)

typedef unsigned long long ull;

__device__ __forceinline__ ull pk2(float x, float y) {
    ull r; asm("mov.b64 %0, {%1, %2};" : "=l"(r) : "f"(x), "f"(y)); return r;
}
__device__ __forceinline__ void upk2(ull v, float& x, float& y) {
    asm("mov.b64 {%0, %1}, %2;" : "=f"(x), "=f"(y) : "l"(v));
}
__device__ __forceinline__ void fma2(ull& d, ull a, ull b) {
    asm("fma.rn.f32x2 %0, %1, %2, %0;" : "+l"(d) : "l"(a), "l"(b));
}
__device__ __forceinline__ float tanhax(float x) {
    float r; asm("tanh.approx.f32 %0, %1;" : "=f"(r) : "f"(x)); return r;
}
__device__ __forceinline__ float sig_t(float x) {   // sigmoid via MUFU.TANH
    return fmaf(0.5f, tanhax(0.5f * x), 0.5f);
}
__device__ __forceinline__ float tanh_ex(float x) { // exact-ish tanh for cell state
    return __fdividef(2.f, 1.f + __expf(-2.f * x)) - 1.f;
}

// One batch-pair of the LSTM cell update (gates in a[4][p] as f32x2 pairs).
__device__ __forceinline__ void cell_pair(ull a[4][4], float c[8], float hv[8], int p) {
    float i0, i1, f0, f1, g0, g1, o0, o1;
    upk2(a[0][p], i0, i1);
    upk2(a[1][p], f0, f1);
    upk2(a[2][p], g0, g1);
    upk2(a[3][p], o0, o1);
    const int k = 2 * p;
    c[k]     = fmaf(sig_t(f0), c[k],     sig_t(i0) * tanhax(g0));
    c[k + 1] = fmaf(sig_t(f1), c[k + 1], sig_t(i1) * tanhax(g1));
    hv[k]     = sig_t(o0) * tanh_ex(c[k]);
    hv[k + 1] = sig_t(o1) * tanh_ex(c[k + 1]);
}

// 64-step MAC accumulating into am[4 gates][4 pairs].
// If CELL: interleave the 4 cell_pair pieces (consuming ac -> c, hv) after
// j-blocks 0,2,4,6 so their MUFU chains hide under subsequent FMA blocks.
template<bool CELL>
__device__ __forceinline__ void mac64(ull am[4][4], const float4* __restrict__ Wp,
                                      const float* __restrict__ hrow, int pb0,
                                      ull ac[4][4], float* c, float* hv) {
#pragma unroll
    for (int blk = 0; blk < 8; blk++) {
#pragma unroll
        for (int jj = 0; jj < 8; jj++) {
            const int j = blk * 8 + jj;
            float4 w = Wp[j * 64];
            ulonglong2 ha = *(const ulonglong2*)(hrow + j * HS + pb0);
            ulonglong2 hb = *(const ulonglong2*)(hrow + j * HS + pb0 + 4);
            ull w0 = pk2(w.x, w.x), w1 = pk2(w.y, w.y);
            ull w2 = pk2(w.z, w.z), w3 = pk2(w.w, w.w);
            fma2(am[0][0], w0, ha.x); fma2(am[0][1], w0, ha.y);
            fma2(am[0][2], w0, hb.x); fma2(am[0][3], w0, hb.y);
            fma2(am[1][0], w1, ha.x); fma2(am[1][1], w1, ha.y);
            fma2(am[1][2], w1, hb.x); fma2(am[1][3], w1, hb.y);
            fma2(am[2][0], w2, ha.x); fma2(am[2][1], w2, ha.y);
            fma2(am[2][2], w2, hb.x); fma2(am[2][3], w2, hb.y);
            fma2(am[3][0], w3, ha.x); fma2(am[3][1], w3, ha.y);
            fma2(am[3][2], w3, hb.x); fma2(am[3][3], w3, hb.y);
        }
        if (CELL && !(blk & 1)) cell_pair(ac, c, hv, blk >> 1);
    }
}

__global__ void __launch_bounds__(NTHR, 1) lstm2_kernel(
    const float* __restrict__ x,
    const float* __restrict__ w_ih0, const float* __restrict__ w_hh0,
    const float* __restrict__ b_ih0, const float* __restrict__ b_hh0,
    const float* __restrict__ w_ih1, const float* __restrict__ w_hh1,
    const float* __restrict__ b_ih1, const float* __restrict__ b_hh1,
    const float* __restrict__ fc_w, const float* __restrict__ fc_b,
    float* __restrict__ out)
{
    extern __shared__ float sm[];
    float4* W0 = (float4*)sm;            // [64 j][64 u] gate-packed Whh0
    float4* W1 = W0 + 64 * 64;           // Wih1
    float4* W2 = W1 + 64 * 64;           // Whh1
    float* h0s = (float*)(W2 + 64 * 64); // [64 u][HS]
    float* h1s = h0s + 64 * HS;          // [64 u][HS]
    float* xs  = h1s + 64 * HS;          // [XCH][16]
    float* sb0 = xs + XCH * 16;          // combined bias L0 [4g][64u]
    float* sb1 = sb0 + 256;              // combined bias L1
    float* swi = sb1 + 256;              // w_ih0 (input size 1)

    const int tid = threadIdx.x;
    const int u   = tid & 63;
    const int pg  = tid >> 6;
    const int pb0 = pg * 8;
    const int b0  = blockIdx.x * BT;

    // ---- stage gate-interleaved transposed weights ----
    for (int e = tid; e < 64 * 64; e += NTHR) {
        int j = e & 63, uu = e >> 6;  // lanes sweep j -> coalesced
        W0[j * 64 + uu] = make_float4(w_hh0[uu * 64 + j],         w_hh0[(64 + uu) * 64 + j],
                                      w_hh0[(128 + uu) * 64 + j], w_hh0[(192 + uu) * 64 + j]);
        W1[j * 64 + uu] = make_float4(w_ih1[uu * 64 + j],         w_ih1[(64 + uu) * 64 + j],
                                      w_ih1[(128 + uu) * 64 + j], w_ih1[(192 + uu) * 64 + j]);
        W2[j * 64 + uu] = make_float4(w_hh1[uu * 64 + j],         w_hh1[(64 + uu) * 64 + j],
                                      w_hh1[(128 + uu) * 64 + j], w_hh1[(192 + uu) * 64 + j]);
    }
    for (int e = tid; e < 64 * HS; e += NTHR) { h0s[e] = 0.f; h1s[e] = 0.f; }
    for (int e = tid; e < 256; e += NTHR) {
        sb0[e] = b_ih0[e] + b_hh0[e];
        sb1[e] = b_ih1[e] + b_hh1[e];
        swi[e] = w_ih0[e];
    }

    float c0[8], c1[8], hv[8];
#pragma unroll
    for (int i = 0; i < 8; i++) { c0[i] = 0.f; c1[i] = 0.f; }

    // prologue: a0(t=0) = bias0 + w_ih0 * x(0)   (h0(-1) = 0)
    ull a0[4][4], a1[4][4];
    {
        float xv[8];
#pragma unroll
        for (int k = 0; k < 8; k++) xv[k] = x[(size_t)(b0 + pb0 + k) * SS];
        __syncthreads();  // smem tables ready (also covers weights)
#pragma unroll
        for (int g = 0; g < 4; g++) {
            ull bp = pk2(sb0[g * 64 + u], sb0[g * 64 + u]);
            ull wp = pk2(swi[g * 64 + u], swi[g * 64 + u]);
#pragma unroll
            for (int p = 0; p < 4; p++) {
                a0[g][p] = bp;
                fma2(a0[g][p], wp, pk2(xv[2 * p], xv[2 * p + 1]));
            }
        }
    }

    for (int t = 0; t < SS; t++) {
        if ((t & (XCH - 1)) == 0) {
            // stage x chunk covering indices [t+1, t+XCH]
            for (int e = tid; e < BT * XCH; e += NTHR) {
                int tc = e & (XCH - 1), b = e >> 6;
                int idx = t + 1 + tc; if (idx > SS - 1) idx = SS - 1;
                xs[tc * 16 + b] = x[(size_t)(b0 + b) * SS + idx];
            }
            __syncthreads();
        }

        // ---- phase A: a1 = bias1 + Whh1*h1(t-1)  ||  cell0(t) from a0 ----
#pragma unroll
        for (int g = 0; g < 4; g++) {
            ull bp = pk2(sb1[g * 64 + u], sb1[g * 64 + u]);
            a1[g][0] = bp; a1[g][1] = bp; a1[g][2] = bp; a1[g][3] = bp;
        }
        mac64<true>(a1, W2 + u, h1s, pb0, a0, c0, hv);
        *(float4*)(h0s + u * HS + pb0)     = make_float4(hv[0], hv[1], hv[2], hv[3]);
        *(float4*)(h0s + u * HS + pb0 + 4) = make_float4(hv[4], hv[5], hv[6], hv[7]);
        __syncthreads();   // h0(t) visible

        // ---- phase B: a1 += Wih1*h0(t); a0(t+1) = ... + Whh0*h0(t) || cell1(t) ----
        mac64<false>(a1, W1 + u, h0s, pb0, a1, c1, hv);
        {
            int tloc = t & (XCH - 1);
            ulonglong2 xa = *(const ulonglong2*)(xs + tloc * 16 + pb0);
            ulonglong2 xb = *(const ulonglong2*)(xs + tloc * 16 + pb0 + 4);
#pragma unroll
            for (int g = 0; g < 4; g++) {
                ull bp = pk2(sb0[g * 64 + u], sb0[g * 64 + u]);
                ull wp = pk2(swi[g * 64 + u], swi[g * 64 + u]);
                a0[g][0] = bp; a0[g][1] = bp; a0[g][2] = bp; a0[g][3] = bp;
                fma2(a0[g][0], wp, xa.x); fma2(a0[g][1], wp, xa.y);
                fma2(a0[g][2], wp, xb.x); fma2(a0[g][3], wp, xb.y);
            }
        }
        mac64<true>(a0, W0 + u, h0s, pb0, a1, c1, hv);
        *(float4*)(h1s + u * HS + pb0)     = make_float4(hv[0], hv[1], hv[2], hv[3]);
        *(float4*)(h1s + u * HS + pb0 + 4) = make_float4(hv[4], hv[5], hv[6], hv[7]);
        __syncthreads();   // h1(t) visible
    }

    // ---- final projection: out = h1(last) @ fc_w^T + fc_b ----
    for (int idx = tid; idx < BT * OUTN; idx += NTHR) {
        int b = idx / OUTN, o = idx - b * OUTN;
        float s = fc_b[o];
#pragma unroll 16
        for (int uu = 0; uu < 64; uu++)
            s += h1s[uu * HS + b] * fc_w[o * 64 + uu];
        out[(size_t)(b0 + b) * OUTN + o] = s;
    }
}

extern "C" void kernel_launch(void* const* d_in, const int* in_sizes, int n_in,
                              void* d_out, int out_size) {
    (void)in_sizes; (void)n_in; (void)out_size;
    const float* x     = (const float*)d_in[0];
    const float* w_ih0 = (const float*)d_in[1];
    const float* w_hh0 = (const float*)d_in[2];
    const float* b_ih0 = (const float*)d_in[3];
    const float* b_hh0 = (const float*)d_in[4];
    const float* w_ih1 = (const float*)d_in[5];
    const float* w_hh1 = (const float*)d_in[6];
    const float* b_ih1 = (const float*)d_in[7];
    const float* b_hh1 = (const float*)d_in[8];
    const float* fc_w  = (const float*)d_in[9];
    const float* fc_b  = (const float*)d_in[10];

    size_t smem = (size_t)(3 * 64 * 64 * 4      // W0,W1,W2 (float4 counted in floats)
                           + 2 * 64 * HS        // h0s, h1s
                           + XCH * 16           // xs
                           + 3 * 256)           // bias/weight tables
                  * sizeof(float);
    cudaFuncSetAttribute(lstm2_kernel, cudaFuncAttributeMaxDynamicSharedMemorySize, (int)smem);
    lstm2_kernel<<<CTAS, NTHR, smem>>>(x, w_ih0, w_hh0, b_ih0, b_hh0,
                                       w_ih1, w_hh1, b_ih1, b_hh1,
                                       fc_w, fc_b, (float*)d_out);
}

// round 6
// speedup vs baseline: 2.4020x; 2.4020x over previous
#include <cuda_runtime.h>

#define SS   512
#define OUTN 12
#define BT   16           // batch per CTA
#define CTAS 128
#define NTHR 256
#define HS   20           // padded h row stride (floats)
#define HSZ  (64 * HS)    // one h buffer
#define XCH  64           // x staging chunk (timesteps)

typedef unsigned long long ull;

__device__ __forceinline__ ull pk2(float x, float y) {
    ull r; asm("mov.b64 %0, {%1, %2};" : "=l"(r) : "f"(x), "f"(y)); return r;
}
__device__ __forceinline__ void upk2(ull v, float& x, float& y) {
    asm("mov.b64 {%0, %1}, %2;" : "=f"(x), "=f"(y) : "l"(v));
}
__device__ __forceinline__ void fma2(ull& d, ull a, ull b) {
    asm("fma.rn.f32x2 %0, %1, %2, %0;" : "+l"(d) : "l"(a), "l"(b));
}
__device__ __forceinline__ float tanhax(float x) {
    float r; asm("tanh.approx.f32 %0, %1;" : "=f"(r) : "f"(x)); return r;
}
__device__ __forceinline__ float sig_t(float x) {   // sigmoid via MUFU.TANH
    return fmaf(0.5f, tanhax(0.5f * x), 0.5f);
}
__device__ __forceinline__ float tanh_ex(float x) { // exact-ish tanh for cell state
    return __fdividef(2.f, 1.f + __expf(-2.f * x)) - 1.f;
}
__device__ __forceinline__ ull shx16(ull v) {
    return __shfl_xor_sync(0xffffffffu, v, 16);
}

// One cell piece (local pair s in {0,1}) for the gate-split layout.
// ao: completed gate accumulators of the OTHER layer's step (2 gates x 4 pairs).
// Thread gh=0 owns (i,f) and updates pairs {0,1}; gh=1 owns (g,o), updates {2,3}.
__device__ __forceinline__ void cell_s(ull ao[2][4], float* c, int gh, int s,
                                       float& hvlo, float& hvhi) {
    ull x0 = gh ? ao[0][s] : ao[0][2 + s];
    ull x1 = gh ? ao[1][s] : ao[1][2 + s];
    ull r0 = shx16(x0);
    ull r1 = shx16(x1);
    ull iv = gh ? r0 : ao[0][s];
    ull fv = gh ? r1 : ao[1][s];
    ull gv = gh ? ao[0][2 + s] : r0;
    ull ov = gh ? ao[1][2 + s] : r1;
    float i0, i1, f0, f1, g0, g1, o0, o1;
    upk2(iv, i0, i1); upk2(fv, f0, f1); upk2(gv, g0, g1); upk2(ov, o0, o1);
    c[2 * s]     = fmaf(sig_t(f0), c[2 * s],     sig_t(i0) * tanhax(g0));
    c[2 * s + 1] = fmaf(sig_t(f1), c[2 * s + 1], sig_t(i1) * tanhax(g1));
    hvlo = sig_t(o0) * tanh_ex(c[2 * s]);
    hvhi = sig_t(o1) * tanh_ex(c[2 * s + 1]);
}

// 64-j MAC into am[2 gates][4 pairs]; optionally interleave the full cell update
// (consuming completed accumulators ao -> c, storing 4 h floats to hdst).
template<bool CELL>
__device__ __forceinline__ void mac64x(ull am[2][4], const float2* __restrict__ Wp,
                                       const float* __restrict__ hrow, int pb0,
                                       ull ao[2][4], float* c, int gh, float* hdst) {
    float hv0, hv1, hv2, hv3;
#pragma unroll
    for (int blk = 0; blk < 8; blk++) {
#pragma unroll
        for (int jj = 0; jj < 8; jj++) {
            const int j = blk * 8 + jj;
            float2 w = Wp[j * 128];
            ulonglong2 ha = *(const ulonglong2*)(hrow + j * HS + pb0);
            ulonglong2 hb = *(const ulonglong2*)(hrow + j * HS + pb0 + 4);
            ull w0 = pk2(w.x, w.x), w1 = pk2(w.y, w.y);
            fma2(am[0][0], w0, ha.x); fma2(am[0][1], w0, ha.y);
            fma2(am[0][2], w0, hb.x); fma2(am[0][3], w0, hb.y);
            fma2(am[1][0], w1, ha.x); fma2(am[1][1], w1, ha.y);
            fma2(am[1][2], w1, hb.x); fma2(am[1][3], w1, hb.y);
        }
        if (CELL && blk == 1) cell_s(ao, c, gh, 0, hv0, hv1);
        if (CELL && blk == 4) cell_s(ao, c, gh, 1, hv2, hv3);
        if (CELL && blk == 6) *(float4*)hdst = make_float4(hv0, hv1, hv2, hv3);
    }
}

__global__ void __launch_bounds__(NTHR, 1) lstm2_kernel(
    const float* __restrict__ x,
    const float* __restrict__ w_ih0, const float* __restrict__ w_hh0,
    const float* __restrict__ b_ih0, const float* __restrict__ b_hh0,
    const float* __restrict__ w_ih1, const float* __restrict__ w_hh1,
    const float* __restrict__ b_ih1, const float* __restrict__ b_hh1,
    const float* __restrict__ fc_w, const float* __restrict__ fc_b,
    float* __restrict__ out)
{
    extern __shared__ float sm[];
    float2* W0 = (float2*)sm;            // [64 j][4 wq][32 lane] float2   (Whh0)
    float2* W1 = W0 + 8192;              // Wih1
    float2* W2 = W1 + 8192;              // Whh1
    float* h0s = (float*)(W2 + 8192);    // [64 j][HS]
    float* h1s = h0s + HSZ;              // [2 slot][64 j][HS]
    float* xs  = h1s + 2 * HSZ;          // [XCH][16]
    float* sb0 = xs + XCH * 16;          // combined bias L0 [4g][64u]
    float* sb1 = sb0 + 256;
    float* swi = sb1 + 256;              // w_ih0 (input size 1)

    const int tid  = threadIdx.x;
    const int lane = tid & 31;
    const int wrp  = tid >> 5;
    const int wq   = wrp & 3;
    const int pg   = wrp >> 2;           // batch half (8 batches)
    const int gh   = lane >> 4;          // gate half: 0 -> {i,f}, 1 -> {g,o}
    const int u    = wq * 16 + (lane & 15);
    const int off  = wq * 32 + lane;     // W float2 offset within a j-row
    const int pb0  = pg * 8;
    const int b0   = blockIdx.x * BT;

    // ---- stage weights: W[j*128 + wq*32 + lane] = (w[2gh][u][j], w[2gh+1][u][j]) ----
    for (int e = tid; e < 8192; e += NTHR) {
        int j = e >> 7, r = e & 127;
        int ln = r & 31, wq2 = r >> 5;
        int gh2 = ln >> 4, u2 = wq2 * 16 + (ln & 15);
        int r0 = (2 * gh2) * 64 + u2, r1 = (2 * gh2 + 1) * 64 + u2;
        W0[e] = make_float2(w_hh0[r0 * 64 + j], w_hh0[r1 * 64 + j]);
        W1[e] = make_float2(w_ih1[r0 * 64 + j], w_ih1[r1 * 64 + j]);
        W2[e] = make_float2(w_hh1[r0 * 64 + j], w_hh1[r1 * 64 + j]);
    }
    for (int e = tid; e < HSZ; e += NTHR) { h0s[e] = 0.f; h1s[e] = 0.f; h1s[HSZ + e] = 0.f; }
    for (int e = tid; e < 256; e += NTHR) {
        sb0[e] = b_ih0[e] + b_hh0[e];
        sb1[e] = b_ih1[e] + b_hh1[e];
        swi[e] = w_ih0[e];
    }
    __syncthreads();

    // per-thread constants for its 2 gates
    ull b0p[2], b1p[2], wip[2];
#pragma unroll
    for (int k = 0; k < 2; k++) {
        int g = 2 * gh + k;
        b0p[k] = pk2(sb0[g * 64 + u], sb0[g * 64 + u]);
        b1p[k] = pk2(sb1[g * 64 + u], sb1[g * 64 + u]);
        wip[k] = pk2(swi[g * 64 + u], swi[g * 64 + u]);
    }

    ull a0[2][4], a1[2][4];
    float c0[4], c1[4];
#pragma unroll
    for (int i = 0; i < 4; i++) {
        c0[i] = 0.f; c1[i] = 0.f;
        a1[0][i] = 0ull; a1[1][i] = 0ull;   // gates1(-1)=0 -> cell1(-1) yields h1=0
    }

    // prologue: a0(0) = bias0 + wih0 * x(0)
    {
        float xv[8];
#pragma unroll
        for (int kk = 0; kk < 8; kk++) xv[kk] = x[(size_t)(b0 + pb0 + kk) * SS];
#pragma unroll
        for (int k = 0; k < 2; k++)
#pragma unroll
            for (int p = 0; p < 4; p++) {
                a0[k][p] = b0p[k];
                fma2(a0[k][p], wip[k], pk2(xv[2 * p], xv[2 * p + 1]));
            }
    }

    const float* Wp0 = (const float2*)W0 + off ? (const float*)0 : (const float*)0; (void)Wp0;

    for (int t = 0; t < SS; t++) {
        if ((t & (XCH - 1)) == 0) {
            __syncthreads();
            for (int e = tid; e < BT * XCH; e += NTHR) {
                int tc = e & (XCH - 1), b = e >> 6;
                int idx = t + 1 + tc; if (idx > SS - 1) idx = SS - 1;
                xs[tc * 16 + b] = x[(size_t)(b0 + b) * SS + idx];
            }
            __syncthreads();
        }

        float* h1w = h1s + (t & 1) * HSZ;        // h1(t-1) lives here this step

        // ---- phase A: a0 += Whh0*h0(t-1)   ||  cell1(t-1) -> h1w ----
        mac64x<true>(a0, W0 + off, h0s, pb0, a1, c1, gh,
                     h1w + u * HS + pb0 + gh * 4);
        __syncthreads();                          // h1(t-1) visible; h0s reads done

        // ---- phase B: a1 = bias1 + Whh1*h1(t-1)  ||  cell0(t) -> h0s ----
#pragma unroll
        for (int k = 0; k < 2; k++) {
            a1[k][0] = b1p[k]; a1[k][1] = b1p[k];
            a1[k][2] = b1p[k]; a1[k][3] = b1p[k];
        }
        mac64x<true>(a1, W2 + off, h1w, pb0, a0, c0, gh,
                     h0s + u * HS + pb0 + gh * 4);
        __syncthreads();                          // h0(t) visible

        // ---- phase C: a1 += Wih1*h0(t);  reseed a0 = bias0 + wih*x(t+1) ----
        mac64x<false>(a1, W1 + off, h0s, pb0, a1, c1, gh, (float*)0);
        {
            int tloc = t & (XCH - 1);
            ulonglong2 xa = *(const ulonglong2*)(xs + tloc * 16 + pb0);
            ulonglong2 xb = *(const ulonglong2*)(xs + tloc * 16 + pb0 + 4);
#pragma unroll
            for (int k = 0; k < 2; k++) {
                a0[k][0] = b0p[k]; a0[k][1] = b0p[k];
                a0[k][2] = b0p[k]; a0[k][3] = b0p[k];
                fma2(a0[k][0], wip[k], xa.x); fma2(a0[k][1], wip[k], xa.y);
                fma2(a0[k][2], wip[k], xb.x); fma2(a0[k][3], wip[k], xb.y);
            }
        }
    }

    // ---- epilogue: cell1(511) -> h1 final (slot SS&1 = 0) ----
    {
        float hv0, hv1, hv2, hv3;
        cell_s(a1, c1, gh, 0, hv0, hv1);
        cell_s(a1, c1, gh, 1, hv2, hv3);
        float* hfin = h1s + (SS & 1) * HSZ;
        *(float4*)(hfin + u * HS + pb0 + gh * 4) = make_float4(hv0, hv1, hv2, hv3);
    }
    __syncthreads();

    // ---- final projection: out = h1(last) @ fc_w^T + fc_b ----
    const float* hf = h1s + (SS & 1) * HSZ;
    for (int idx = tid; idx < BT * OUTN; idx += NTHR) {
        int b = idx / OUTN, o = idx - b * OUTN;
        float s = fc_b[o];
#pragma unroll 16
        for (int uu = 0; uu < 64; uu++)
            s += hf[uu * HS + b] * fc_w[o * 64 + uu];
        out[(size_t)(b0 + b) * OUTN + o] = s;
    }
}

extern "C" void kernel_launch(void* const* d_in, const int* in_sizes, int n_in,
                              void* d_out, int out_size) {
    (void)in_sizes; (void)n_in; (void)out_size;
    const float* x     = (const float*)d_in[0];
    const float* w_ih0 = (const float*)d_in[1];
    const float* w_hh0 = (const float*)d_in[2];
    const float* b_ih0 = (const float*)d_in[3];
    const float* b_hh0 = (const float*)d_in[4];
    const float* w_ih1 = (const float*)d_in[5];
    const float* w_hh1 = (const float*)d_in[6];
    const float* b_ih1 = (const float*)d_in[7];
    const float* b_hh1 = (const float*)d_in[8];
    const float* fc_w  = (const float*)d_in[9];
    const float* fc_b  = (const float*)d_in[10];

    size_t smem = (size_t)(3 * 8192 * 2      // W0,W1,W2 (float2 -> counted in floats)
                           + 3 * HSZ         // h0s + h1s(double)
                           + XCH * 16        // xs
                           + 3 * 256)        // bias/wih tables
                  * sizeof(float);
    cudaFuncSetAttribute(lstm2_kernel, cudaFuncAttributeMaxDynamicSharedMemorySize, (int)smem);
    lstm2_kernel<<<CTAS, NTHR, smem>>>(x, w_ih0, w_hh0, b_ih0, b_hh0,
                                       w_ih1, w_hh1, b_ih1, b_hh1,
                                       fc_w, fc_b, (float*)d_out);
}

// round 7
// speedup vs baseline: 2.4541x; 1.0217x over previous
#include <cuda_runtime.h>

#define SS   512
#define OUTN 12
#define BT   16           // batch per CTA
#define CTAS 128
#define NTHR 256
#define HS   20           // padded h row stride (floats)
#define HSZ  (64 * HS)    // one h buffer
#define XCH  64           // x staging chunk (timesteps)

typedef unsigned long long ull;

__device__ __forceinline__ ull pk2(float x, float y) {
    ull r; asm("mov.b64 %0, {%1, %2};" : "=l"(r) : "f"(x), "f"(y)); return r;
}
__device__ __forceinline__ void upk2(ull v, float& x, float& y) {
    asm("mov.b64 {%0, %1}, %2;" : "=f"(x), "=f"(y) : "l"(v));
}
__device__ __forceinline__ void fma2(ull& d, ull a, ull b) {
    asm("fma.rn.f32x2 %0, %1, %2, %0;" : "+l"(d) : "l"(a), "l"(b));
}
__device__ __forceinline__ float tanhax(float x) {
    float r; asm("tanh.approx.f32 %0, %1;" : "=f"(r) : "f"(x)); return r;
}
__device__ __forceinline__ float sig_t(float x) {   // sigmoid via MUFU.TANH
    return fmaf(0.5f, tanhax(0.5f * x), 0.5f);
}
__device__ __forceinline__ float tanh_ex(float x) { // exact-ish tanh for cell state
    return __fdividef(2.f, 1.f + __expf(-2.f * x)) - 1.f;
}

// One pair-piece (s in {0,1}) of the fully thread-local cell update.
// a[4 gates][2 pairs] holds i,f,g,o accumulators for 4 batch scalars.
__device__ __forceinline__ void cell_s(ull a[4][2], float* c, int s,
                                       float& hvlo, float& hvhi) {
    float i0, i1, f0, f1, g0, g1, o0, o1;
    upk2(a[0][s], i0, i1);
    upk2(a[1][s], f0, f1);
    upk2(a[2][s], g0, g1);
    upk2(a[3][s], o0, o1);
    c[2 * s]     = fmaf(sig_t(f0), c[2 * s],     sig_t(i0) * tanhax(g0));
    c[2 * s + 1] = fmaf(sig_t(f1), c[2 * s + 1], sig_t(i1) * tanhax(g1));
    hvlo = sig_t(o0) * tanh_ex(c[2 * s]);
    hvhi = sig_t(o1) * tanh_ex(c[2 * s + 1]);
}

// 64-j MAC into am[4][2]; optionally interleave the other accumulator's cell
// update (ao -> c, h written to hdst as float4) under the FMA stream.
template<bool CELL>
__device__ __forceinline__ void mac64q(ull am[4][2], const float4* __restrict__ Wp,
                                       const float* __restrict__ hrow, int qb,
                                       ull ao[4][2], float* c, float* hdst) {
    float hv0, hv1, hv2, hv3;
#pragma unroll
    for (int blk = 0; blk < 8; blk++) {
#pragma unroll
        for (int jj = 0; jj < 8; jj++) {
            const int j = blk * 8 + jj;
            float4 w = Wp[j * 64];
            ulonglong2 hh = *(const ulonglong2*)(hrow + j * HS + qb);
            ull w0 = pk2(w.x, w.x), w1 = pk2(w.y, w.y);
            ull w2 = pk2(w.z, w.z), w3 = pk2(w.w, w.w);
            fma2(am[0][0], w0, hh.x); fma2(am[0][1], w0, hh.y);
            fma2(am[1][0], w1, hh.x); fma2(am[1][1], w1, hh.y);
            fma2(am[2][0], w2, hh.x); fma2(am[2][1], w2, hh.y);
            fma2(am[3][0], w3, hh.x); fma2(am[3][1], w3, hh.y);
        }
        if (CELL && blk == 1) cell_s(ao, c, 0, hv0, hv1);
        if (CELL && blk == 4) cell_s(ao, c, 1, hv2, hv3);
        if (CELL && blk == 6) *(float4*)hdst = make_float4(hv0, hv1, hv2, hv3);
    }
}

__global__ void __launch_bounds__(NTHR, 1) lstm2_kernel(
    const float* __restrict__ x,
    const float* __restrict__ w_ih0, const float* __restrict__ w_hh0,
    const float* __restrict__ b_ih0, const float* __restrict__ b_hh0,
    const float* __restrict__ w_ih1, const float* __restrict__ w_hh1,
    const float* __restrict__ b_ih1, const float* __restrict__ b_hh1,
    const float* __restrict__ fc_w, const float* __restrict__ fc_b,
    float* __restrict__ out)
{
    extern __shared__ float sm[];
    float4* W0 = (float4*)sm;            // [64 j][64 u] gate-packed Whh0
    float4* W1 = W0 + 64 * 64;           // Wih1
    float4* W2 = W1 + 64 * 64;           // Whh1
    float* h0s = (float*)(W2 + 64 * 64); // [64 u][HS]
    float* h1s = h0s + HSZ;              // [2 slot][64 u][HS]
    float* xs  = h1s + 2 * HSZ;          // [XCH][16]
    float* sb0 = xs + XCH * 16;          // combined bias L0 [4g][64u]
    float* sb1 = sb0 + 256;
    float* swi = sb1 + 256;              // w_ih0 (input size 1)

    const int tid  = threadIdx.x;
    const int lane = tid & 31;
    const int wrp  = tid >> 5;
    const int u    = wrp * 8 + (lane & 7);   // hidden unit owned
    const int q    = lane >> 3;              // batch quad 0..3
    const int qb   = q * 4;                  // first batch of quad
    const int b0   = blockIdx.x * BT;

    // ---- stage gate-interleaved transposed weights ----
    for (int e = tid; e < 64 * 64; e += NTHR) {
        int j = e & 63, uu = e >> 6;  // lanes sweep j -> coalesced gmem
        W0[j * 64 + uu] = make_float4(w_hh0[uu * 64 + j],         w_hh0[(64 + uu) * 64 + j],
                                      w_hh0[(128 + uu) * 64 + j], w_hh0[(192 + uu) * 64 + j]);
        W1[j * 64 + uu] = make_float4(w_ih1[uu * 64 + j],         w_ih1[(64 + uu) * 64 + j],
                                      w_ih1[(128 + uu) * 64 + j], w_ih1[(192 + uu) * 64 + j]);
        W2[j * 64 + uu] = make_float4(w_hh1[uu * 64 + j],         w_hh1[(64 + uu) * 64 + j],
                                      w_hh1[(128 + uu) * 64 + j], w_hh1[(192 + uu) * 64 + j]);
    }
    for (int e = tid; e < HSZ; e += NTHR) {
        h0s[e] = 0.f; h1s[e] = 0.f; h1s[HSZ + e] = 0.f;
    }
    for (int e = tid; e < 256; e += NTHR) {
        sb0[e] = b_ih0[e] + b_hh0[e];
        sb1[e] = b_ih1[e] + b_hh1[e];
        swi[e] = w_ih0[e];
    }
    __syncthreads();

    // per-thread constants: 4 gates, duplicated f32x2
    ull b0p[4], b1p[4], wip[4];
#pragma unroll
    for (int g = 0; g < 4; g++) {
        b0p[g] = pk2(sb0[g * 64 + u], sb0[g * 64 + u]);
        b1p[g] = pk2(sb1[g * 64 + u], sb1[g * 64 + u]);
        wip[g] = pk2(swi[g * 64 + u], swi[g * 64 + u]);
    }

    ull a0[4][2], a1[4][2];
    float c0[4], c1[4];
#pragma unroll
    for (int g = 0; g < 4; g++) { a1[g][0] = 0ull; a1[g][1] = 0ull; }
#pragma unroll
    for (int i = 0; i < 4; i++) { c0[i] = 0.f; c1[i] = 0.f; }

    // prologue: a0(0) = bias0 + wih0 * x(0)   (h0(-1)=0)
    {
        float xv[4];
#pragma unroll
        for (int k = 0; k < 4; k++) xv[k] = x[(size_t)(b0 + qb + k) * SS];
        ull xp0 = pk2(xv[0], xv[1]), xp1 = pk2(xv[2], xv[3]);
#pragma unroll
        for (int g = 0; g < 4; g++) {
            a0[g][0] = b0p[g]; a0[g][1] = b0p[g];
            fma2(a0[g][0], wip[g], xp0);
            fma2(a0[g][1], wip[g], xp1);
        }
    }

    for (int t = 0; t < SS; t++) {
        if ((t & (XCH - 1)) == 0) {
            __syncthreads();
            for (int e = tid; e < BT * XCH; e += NTHR) {
                int tc = e & (XCH - 1), b = e >> 6;
                int idx = t + 1 + tc; if (idx > SS - 1) idx = SS - 1;
                xs[tc * 16 + b] = x[(size_t)(b0 + b) * SS + idx];
            }
            __syncthreads();
        }

        float* h1w = h1s + (t & 1) * HSZ;   // h1(t-1) produced here this step

        // ---- phase A: a0 += Whh0*h0(t-1)   ||  cell1(t-1) -> h1w ----
        mac64q<true>(a0, W0 + u, h0s, qb, a1, c1, h1w + u * HS + qb);
        __syncthreads();                    // h1(t-1) visible; h0(t-1) reads done

        // ---- phase B: a1 = bias1 + Whh1*h1(t-1)  ||  cell0(t) -> h0s ----
#pragma unroll
        for (int g = 0; g < 4; g++) { a1[g][0] = b1p[g]; a1[g][1] = b1p[g]; }
        mac64q<true>(a1, W2 + u, h1w, qb, a0, c0, h0s + u * HS + qb);
        __syncthreads();                    // h0(t) visible

        // ---- phase C: a1 += Wih1*h0(t);  reseed a0 = bias0 + wih*x(t+1) ----
        mac64q<false>(a1, W1 + u, h0s, qb, a1, c1, (float*)0);
        {
            int tloc = t & (XCH - 1);
            ull xp0 = *(const ull*)(xs + tloc * 16 + qb);
            ull xp1 = *(const ull*)(xs + tloc * 16 + qb + 2);
#pragma unroll
            for (int g = 0; g < 4; g++) {
                a0[g][0] = b0p[g]; a0[g][1] = b0p[g];
                fma2(a0[g][0], wip[g], xp0);
                fma2(a0[g][1], wip[g], xp1);
            }
        }
    }

    // ---- epilogue: cell1(511) -> final h1 (slot 0) ----
    {
        float hv0, hv1, hv2, hv3;
        cell_s(a1, c1, 0, hv0, hv1);
        cell_s(a1, c1, 1, hv2, hv3);
        *(float4*)(h1s + u * HS + qb) = make_float4(hv0, hv1, hv2, hv3);
    }
    __syncthreads();

    // ---- final projection: out = h1(last) @ fc_w^T + fc_b ----
    for (int idx = tid; idx < BT * OUTN; idx += NTHR) {
        int b = idx / OUTN, o = idx - b * OUTN;
        float s = fc_b[o];
#pragma unroll 16
        for (int uu = 0; uu < 64; uu++)
            s += h1s[uu * HS + b] * fc_w[o * 64 + uu];
        out[(size_t)(b0 + b) * OUTN + o] = s;
    }
}

extern "C" void kernel_launch(void* const* d_in, const int* in_sizes, int n_in,
                              void* d_out, int out_size) {
    (void)in_sizes; (void)n_in; (void)out_size;
    const float* x     = (const float*)d_in[0];
    const float* w_ih0 = (const float*)d_in[1];
    const float* w_hh0 = (const float*)d_in[2];
    const float* b_ih0 = (const float*)d_in[3];
    const float* b_hh0 = (const float*)d_in[4];
    const float* w_ih1 = (const float*)d_in[5];
    const float* w_hh1 = (const float*)d_in[6];
    const float* b_ih1 = (const float*)d_in[7];
    const float* b_hh1 = (const float*)d_in[8];
    const float* fc_w  = (const float*)d_in[9];
    const float* fc_b  = (const float*)d_in[10];

    size_t smem = (size_t)(3 * 64 * 64 * 4    // W0,W1,W2 (float4 -> floats)
                           + 3 * HSZ          // h0s + h1s double buffer
                           + XCH * 16         // xs
                           + 3 * 256)         // bias/wih tables
                  * sizeof(float);
    cudaFuncSetAttribute(lstm2_kernel, cudaFuncAttributeMaxDynamicSharedMemorySize, (int)smem);
    lstm2_kernel<<<CTAS, NTHR, smem>>>(x, w_ih0, w_hh0, b_ih0, b_hh0,
                                       w_ih1, w_hh1, b_ih1, b_hh1,
                                       fc_w, fc_b, (float*)d_out);
}

// round 8
// speedup vs baseline: 2.4870x; 1.0134x over previous
#include <cuda_runtime.h>

#define SS   512
#define OUTN 12
#define BT   16           // batch per CTA
#define CTAS 128
#define NTHR 256
#define HS   20           // padded h row stride (floats)
#define HSZ  (64 * HS)    // one h buffer
#define XCH  64           // x staging chunk (timesteps)

typedef unsigned long long ull;

__device__ __forceinline__ ull pk2(float x, float y) {
    ull r; asm("mov.b64 %0, {%1, %2};" : "=l"(r) : "f"(x), "f"(y)); return r;
}
__device__ __forceinline__ void upk2(ull v, float& x, float& y) {
    asm("mov.b64 {%0, %1}, %2;" : "=f"(x), "=f"(y) : "l"(v));
}
__device__ __forceinline__ void fma2(ull& d, ull a, ull b) {
    asm("fma.rn.f32x2 %0, %1, %2, %0;" : "+l"(d) : "l"(a), "l"(b));
}
__device__ __forceinline__ float tanhax(float x) {
    float r; asm("tanh.approx.f32 %0, %1;" : "=f"(r) : "f"(x)); return r;
}
__device__ __forceinline__ float sig_t(float x) {   // sigmoid via MUFU.TANH
    return fmaf(0.5f, tanhax(0.5f * x), 0.5f);
}

// One pair-piece (s in {0,1}) of the fully thread-local cell update.
__device__ __forceinline__ void cell_s(ull a[4][2], float* c, int s,
                                       float& hvlo, float& hvhi) {
    float i0, i1, f0, f1, g0, g1, o0, o1;
    upk2(a[0][s], i0, i1);
    upk2(a[1][s], f0, f1);
    upk2(a[2][s], g0, g1);
    upk2(a[3][s], o0, o1);
    c[2 * s]     = fmaf(sig_t(f0), c[2 * s],     sig_t(i0) * tanhax(g0));
    c[2 * s + 1] = fmaf(sig_t(f1), c[2 * s + 1], sig_t(i1) * tanhax(g1));
    hvlo = sig_t(o0) * tanhax(c[2 * s]);
    hvhi = sig_t(o1) * tanhax(c[2 * s + 1]);
}

// 64-j MAC into am[4][2] with explicit 2-deep (W,h) register prefetch.
// If CELL: interleave the other accumulator's cell update under the stream.
template<bool CELL>
__device__ __forceinline__ void mac64q(ull am[4][2], const float4* __restrict__ Wp,
                                       const float* __restrict__ hrow, int qb,
                                       ull ao[4][2], float* c, float* hdst) {
    float hv0, hv1, hv2, hv3;
    float4 wbuf[2];
    ulonglong2 hbuf[2];
    // prime the pipeline (j = 0, 1)
    wbuf[0] = Wp[0];
    hbuf[0] = *(const ulonglong2*)(hrow + qb);
    wbuf[1] = Wp[64];
    hbuf[1] = *(const ulonglong2*)(hrow + HS + qb);
#pragma unroll
    for (int blk = 0; blk < 8; blk++) {
#pragma unroll
        for (int jj = 0; jj < 8; jj++) {
            const int j = blk * 8 + jj;
            const int cb = j & 1;
            float4 w = wbuf[cb];
            ulonglong2 hh = hbuf[cb];
            const int jn = (j + 2) & 63;     // wraps harmlessly on last iters
            wbuf[cb] = Wp[jn * 64];
            hbuf[cb] = *(const ulonglong2*)(hrow + jn * HS + qb);
            ull w0 = pk2(w.x, w.x), w1 = pk2(w.y, w.y);
            ull w2 = pk2(w.z, w.z), w3 = pk2(w.w, w.w);
            fma2(am[0][0], w0, hh.x); fma2(am[0][1], w0, hh.y);
            fma2(am[1][0], w1, hh.x); fma2(am[1][1], w1, hh.y);
            fma2(am[2][0], w2, hh.x); fma2(am[2][1], w2, hh.y);
            fma2(am[3][0], w3, hh.x); fma2(am[3][1], w3, hh.y);
        }
        if (CELL && blk == 0) cell_s(ao, c, 0, hv0, hv1);
        if (CELL && blk == 3) cell_s(ao, c, 1, hv2, hv3);
        if (CELL && blk == 5) *(float4*)hdst = make_float4(hv0, hv1, hv2, hv3);
    }
}

__global__ void __launch_bounds__(NTHR, 1) lstm2_kernel(
    const float* __restrict__ x,
    const float* __restrict__ w_ih0, const float* __restrict__ w_hh0,
    const float* __restrict__ b_ih0, const float* __restrict__ b_hh0,
    const float* __restrict__ w_ih1, const float* __restrict__ w_hh1,
    const float* __restrict__ b_ih1, const float* __restrict__ b_hh1,
    const float* __restrict__ fc_w, const float* __restrict__ fc_b,
    float* __restrict__ out)
{
    extern __shared__ float sm[];
    float4* W0 = (float4*)sm;            // [64 j][64 u] gate-packed Whh0
    float4* W1 = W0 + 64 * 64;           // Wih1
    float4* W2 = W1 + 64 * 64;           // Whh1
    float* h0s = (float*)(W2 + 64 * 64); // [64 u][HS]
    float* h1s = h0s + HSZ;              // [2 slot][64 u][HS]
    float* xs  = h1s + 2 * HSZ;          // [XCH][16]
    float* sb0 = xs + XCH * 16;          // combined bias L0 [4g][64u]
    float* sb1 = sb0 + 256;
    float* swi = sb1 + 256;              // w_ih0 (input size 1)

    const int tid  = threadIdx.x;
    const int lane = tid & 31;
    const int wrp  = tid >> 5;
    const int u    = wrp * 8 + (lane & 7);   // hidden unit owned
    const int q    = lane >> 3;              // batch quad 0..3
    const int qb   = q * 4;                  // first batch of quad
    const int b0   = blockIdx.x * BT;

    // ---- stage gate-interleaved transposed weights ----
    for (int e = tid; e < 64 * 64; e += NTHR) {
        int j = e & 63, uu = e >> 6;  // lanes sweep j -> coalesced gmem
        W0[j * 64 + uu] = make_float4(w_hh0[uu * 64 + j],         w_hh0[(64 + uu) * 64 + j],
                                      w_hh0[(128 + uu) * 64 + j], w_hh0[(192 + uu) * 64 + j]);
        W1[j * 64 + uu] = make_float4(w_ih1[uu * 64 + j],         w_ih1[(64 + uu) * 64 + j],
                                      w_ih1[(128 + uu) * 64 + j], w_ih1[(192 + uu) * 64 + j]);
        W2[j * 64 + uu] = make_float4(w_hh1[uu * 64 + j],         w_hh1[(64 + uu) * 64 + j],
                                      w_hh1[(128 + uu) * 64 + j], w_hh1[(192 + uu) * 64 + j]);
    }
    for (int e = tid; e < HSZ; e += NTHR) {
        h0s[e] = 0.f; h1s[e] = 0.f; h1s[HSZ + e] = 0.f;
    }
    for (int e = tid; e < 256; e += NTHR) {
        sb0[e] = b_ih0[e] + b_hh0[e];
        sb1[e] = b_ih1[e] + b_hh1[e];
        swi[e] = w_ih0[e];
    }
    __syncthreads();

    // per-thread constants: 4 gates, duplicated f32x2
    ull b0p[4], b1p[4], wip[4];
#pragma unroll
    for (int g = 0; g < 4; g++) {
        b0p[g] = pk2(sb0[g * 64 + u], sb0[g * 64 + u]);
        b1p[g] = pk2(sb1[g * 64 + u], sb1[g * 64 + u]);
        wip[g] = pk2(swi[g * 64 + u], swi[g * 64 + u]);
    }

    ull a0[4][2], a1[4][2];
    float c0[4], c1[4];
#pragma unroll
    for (int g = 0; g < 4; g++) { a1[g][0] = 0ull; a1[g][1] = 0ull; }
#pragma unroll
    for (int i = 0; i < 4; i++) { c0[i] = 0.f; c1[i] = 0.f; }

    // prologue: a0(0) = bias0 + wih0 * x(0)   (h0(-1)=0)
    {
        float xv[4];
#pragma unroll
        for (int k = 0; k < 4; k++) xv[k] = x[(size_t)(b0 + qb + k) * SS];
        ull xp0 = pk2(xv[0], xv[1]), xp1 = pk2(xv[2], xv[3]);
#pragma unroll
        for (int g = 0; g < 4; g++) {
            a0[g][0] = b0p[g]; a0[g][1] = b0p[g];
            fma2(a0[g][0], wip[g], xp0);
            fma2(a0[g][1], wip[g], xp1);
        }
    }

    for (int t = 0; t < SS; t++) {
        if ((t & (XCH - 1)) == 0) {
            __syncthreads();
            for (int e = tid; e < BT * XCH; e += NTHR) {
                int tc = e & (XCH - 1), b = e >> 6;
                int idx = t + 1 + tc; if (idx > SS - 1) idx = SS - 1;
                xs[tc * 16 + b] = x[(size_t)(b0 + b) * SS + idx];
            }
            __syncthreads();
        }

        float* h1w = h1s + (t & 1) * HSZ;   // h1(t-1) produced here this step

        // ---- phase A: a0 += Whh0*h0(t-1)   ||  cell1(t-1) -> h1w ----
        mac64q<true>(a0, W0 + u, h0s, qb, a1, c1, h1w + u * HS + qb);
        __syncthreads();                    // h1(t-1) visible; h0(t-1) reads done

        // ---- phase B: a1 = bias1 + Whh1*h1(t-1)  ||  cell0(t) -> h0s ----
#pragma unroll
        for (int g = 0; g < 4; g++) { a1[g][0] = b1p[g]; a1[g][1] = b1p[g]; }
        mac64q<true>(a1, W2 + u, h1w, qb, a0, c0, h0s + u * HS + qb);
        __syncthreads();                    // h0(t) visible

        // ---- phase C: a1 += Wih1*h0(t);  reseed a0 = bias0 + wih*x(t+1) ----
        mac64q<false>(a1, W1 + u, h0s, qb, a1, c1, (float*)0);
        {
            int tloc = t & (XCH - 1);
            ull xp0 = *(const ull*)(xs + tloc * 16 + qb);
            ull xp1 = *(const ull*)(xs + tloc * 16 + qb + 2);
#pragma unroll
            for (int g = 0; g < 4; g++) {
                a0[g][0] = b0p[g]; a0[g][1] = b0p[g];
                fma2(a0[g][0], wip[g], xp0);
                fma2(a0[g][1], wip[g], xp1);
            }
        }
    }

    // ---- epilogue: cell1(511) -> final h1 (slot 0) ----
    {
        float hv0, hv1, hv2, hv3;
        cell_s(a1, c1, 0, hv0, hv1);
        cell_s(a1, c1, 1, hv2, hv3);
        *(float4*)(h1s + u * HS + qb) = make_float4(hv0, hv1, hv2, hv3);
    }
    __syncthreads();

    // ---- final projection: out = h1(last) @ fc_w^T + fc_b ----
    for (int idx = tid; idx < BT * OUTN; idx += NTHR) {
        int b = idx / OUTN, o = idx - b * OUTN;
        float s = fc_b[o];
#pragma unroll 16
        for (int uu = 0; uu < 64; uu++)
            s += h1s[uu * HS + b] * fc_w[o * 64 + uu];
        out[(size_t)(b0 + b) * OUTN + o] = s;
    }
}

extern "C" void kernel_launch(void* const* d_in, const int* in_sizes, int n_in,
                              void* d_out, int out_size) {
    (void)in_sizes; (void)n_in; (void)out_size;
    const float* x     = (const float*)d_in[0];
    const float* w_ih0 = (const float*)d_in[1];
    const float* w_hh0 = (const float*)d_in[2];
    const float* b_ih0 = (const float*)d_in[3];
    const float* b_hh0 = (const float*)d_in[4];
    const float* w_ih1 = (const float*)d_in[5];
    const float* w_hh1 = (const float*)d_in[6];
    const float* b_ih1 = (const float*)d_in[7];
    const float* b_hh1 = (const float*)d_in[8];
    const float* fc_w  = (const float*)d_in[9];
    const float* fc_b  = (const float*)d_in[10];

    size_t smem = (size_t)(3 * 64 * 64 * 4    // W0,W1,W2 (float4 -> floats)
                           + 3 * HSZ          // h0s + h1s double buffer
                           + XCH * 16         // xs
                           + 3 * 256)         // bias/wih tables
                  * sizeof(float);
    cudaFuncSetAttribute(lstm2_kernel, cudaFuncAttributeMaxDynamicSharedMemorySize, (int)smem);
    lstm2_kernel<<<CTAS, NTHR, smem>>>(x, w_ih0, w_hh0, b_ih0, b_hh0,
                                       w_ih1, w_hh1, b_ih1, b_hh1,
                                       fc_w, fc_b, (float*)d_out);
}

// round 9
// speedup vs baseline: 5.2192x; 2.0985x over previous
#include <cuda_runtime.h>
#include <cstdint>

#define SS   512
#define OUTN 12
#define CTAS 128
#define NTHR 256
#define XCH  64

typedef uint32_t u32;

__device__ __forceinline__ u32 tf32r(float x) {
    u32 r; asm("cvt.rna.tf32.f32 %0, %1;" : "=r"(r) : "f"(x)); return r;
}
__device__ __forceinline__ float tanhax(float x) {
    float r; asm("tanh.approx.f32 %0, %1;" : "=f"(r) : "f"(x)); return r;
}
__device__ __forceinline__ float sig_t(float x) { return fmaf(0.5f, tanhax(0.5f * x), 0.5f); }

__device__ __forceinline__ void mma8(float d[4], const u32 a[4], u32 b0, u32 b1) {
    asm volatile("mma.sync.aligned.m16n8k8.row.col.f32.tf32.tf32.f32 "
                 "{%0,%1,%2,%3}, {%4,%5,%6,%7}, {%8,%9}, {%0,%1,%2,%3};"
                 : "+f"(d[0]), "+f"(d[1]), "+f"(d[2]), "+f"(d[3])
                 : "r"(a[0]), "r"(a[1]), "r"(a[2]), "r"(a[3]), "r"(b0), "r"(b1));
}

// round-to-nearest f32 -> bf16 (upper 16 bits), deterministic manual pack
__device__ __forceinline__ u32 bf16rn(float x) {
    u32 u = __float_as_uint(x);
    u += 0x7fffu + ((u >> 16) & 1u);
    return u >> 16;
}

// gate-interleaved column n = 4*u + g  ->  global weight row g*64 + u
__device__ __forceinline__ int grow(int n) { return (n & 3) * 64 + (n >> 2); }

// smem float offsets
#define OF_AF0   0
#define OF_AF1   1024
#define OF_XS    2048
#define OF_HFIN  3072
#define OF_SI0   4096     // [w][nt][lane][4] : bias0 n0, bias0 n1, wih0 n0, wih0 n1
#define OF_SI1   8192     // [w][nt][lane][2] : bias1 n0, bias1 n1
#define OF_W1HI  10240    // [w][nt][kt][lane][2] u32-pairs stored as 2 floats
#define OF_L0    26624    // [w][nt][kt][lane]  bf16x2 lo residual (b0 low, b1 high)
#define OF_L1    34816
#define OF_L2    43008
#define SMEMF    51200    // 200 KB

#define FRAG(w, nt, kt, ln) (((((w) * 4 + (nt)) * 8 + (kt)) * 32) + (ln))

__global__ void __launch_bounds__(NTHR, 1) lstm2_mma(
    const float* __restrict__ x,
    const float* __restrict__ w_ih0, const float* __restrict__ w_hh0,
    const float* __restrict__ b_ih0, const float* __restrict__ b_hh0,
    const float* __restrict__ w_ih1, const float* __restrict__ w_hh1,
    const float* __restrict__ b_ih1, const float* __restrict__ b_hh1,
    const float* __restrict__ fc_w, const float* __restrict__ fc_b,
    float* __restrict__ out)
{
    extern __shared__ float sm[];
    float* Af0  = sm + OF_AF0;
    float* Af1  = sm + OF_AF1;
    float* xs   = sm + OF_XS;
    float* hfin = sm + OF_HFIN;
    float* si0  = sm + OF_SI0;
    float* si1  = sm + OF_SI1;
    u32*   w1h  = (u32*)(sm + OF_W1HI);
    u32*   lo0  = (u32*)(sm + OF_L0);
    u32*   lo1  = (u32*)(sm + OF_L1);
    u32*   lo2  = (u32*)(sm + OF_L2);

    const int tid  = threadIdx.x;
    const int lane = tid & 31;
    const int w    = tid >> 5;          // warp: owns cols [32w, 32w+32)
    const int g    = lane >> 2;         // group id (row within 8)
    const int tg   = lane & 3;          // thread-in-group
    const int evn  = (tg & 1) == 0;
    const int rr   = g + 8 * (tg & 1);  // batch row this lane cells
    const int uoff = tg >> 1;           // unit-within-ntile
    const int b0g  = blockIdx.x * 16;   // first global batch of CTA

    // ---------------- one-time staging ----------------
    // zero Af0/Af1 (h(-1) = 0)
    for (int e = tid; e < 2048; e += NTHR) sm[e] = 0.f;

    // resident hi-frags for Whh0, Whh1
    u32 rh0[4][8][2], rh2[4][8][2];
#pragma unroll
    for (int nt = 0; nt < 4; nt++) {
        const int n  = w * 32 + nt * 8 + g;
        const int gr = grow(n);
#pragma unroll
        for (int kt = 0; kt < 8; kt++) {
            const int k0 = kt * 8 + tg, k1 = k0 + 4;
            // Whh0
            float v0 = w_hh0[gr * 64 + k0], v1 = w_hh0[gr * 64 + k1];
            u32 a0 = tf32r(v0), a1 = tf32r(v1);
            rh0[nt][kt][0] = a0; rh0[nt][kt][1] = a1;
            lo0[FRAG(w, nt, kt, lane)] =
                (bf16rn(v1 - __uint_as_float(a1)) << 16) | bf16rn(v0 - __uint_as_float(a0));
            // Whh1
            v0 = w_hh1[gr * 64 + k0]; v1 = w_hh1[gr * 64 + k1];
            a0 = tf32r(v0); a1 = tf32r(v1);
            rh2[nt][kt][0] = a0; rh2[nt][kt][1] = a1;
            lo2[FRAG(w, nt, kt, lane)] =
                (bf16rn(v1 - __uint_as_float(a1)) << 16) | bf16rn(v0 - __uint_as_float(a0));
            // Wih1 (hi in smem)
            v0 = w_ih1[gr * 64 + k0]; v1 = w_ih1[gr * 64 + k1];
            a0 = tf32r(v0); a1 = tf32r(v1);
            w1h[FRAG(w, nt, kt, lane) * 2 + 0] = a0;
            w1h[FRAG(w, nt, kt, lane) * 2 + 1] = a1;
            lo1[FRAG(w, nt, kt, lane)] =
                (bf16rn(v1 - __uint_as_float(a1)) << 16) | bf16rn(v0 - __uint_as_float(a0));
        }
        // init tables (bias, input weight) for this warp's cols
        const int n0 = w * 32 + nt * 8 + 2 * tg, n1 = n0 + 1;
        const int g0 = grow(n0), g1 = grow(n1);
        float* p0 = si0 + (((w * 4 + nt) * 32) + lane) * 4;
        p0[0] = b_ih0[g0] + b_hh0[g0];
        p0[1] = b_ih0[g1] + b_hh0[g1];
        p0[2] = w_ih0[g0];                 // INPUT_SIZE == 1
        p0[3] = w_ih0[g1];
        float* p1 = si1 + (((w * 4 + nt) * 32) + lane) * 2;
        p1[0] = b_ih1[g0] + b_hh1[g0];
        p1[1] = b_ih1[g1] + b_hh1[g1];
    }

    // per-lane Af write slots (kt == w for this warp's units)
    int lanep[4], regn[4];
#pragma unroll
    for (int nt = 0; nt < 4; nt++) {
        const int ct = 2 * nt + uoff;
        lanep[nt] = ((rr & 7) << 2) | (ct & 3);
        regn[nt]  = (nt >= 2 ? 2 : 0) + (rr >= 8 ? 1 : 0);
    }

    float c0[4] = {0.f, 0.f, 0.f, 0.f}, c1[4] = {0.f, 0.f, 0.f, 0.f};
    float hv1[4] = {0.f, 0.f, 0.f, 0.f};
    __syncthreads();

    // ---------------- recurrence ----------------
    for (int t = 0; t < SS; t++) {
        if ((t & (XCH - 1)) == 0) {       // refill x chunk [t, t+XCH)
            for (int e = tid; e < 16 * XCH; e += NTHR) {
                int tc = e & (XCH - 1), b = e >> 6;
                xs[tc * 16 + b] = x[(size_t)(b0g + b) * SS + t + tc];
            }
            __syncthreads();
        }
        const int tloc = t & (XCH - 1);
        const float xg  = xs[tloc * 16 + g];
        const float xg8 = xs[tloc * 16 + g + 8];

        // ---- D0 = bias0 + wih0*x_t ;  D1 = bias1 ----
        float D0[4][4], D1[4][4];
#pragma unroll
        for (int nt = 0; nt < 4; nt++) {
            float4 ini = *(const float4*)(si0 + (((w * 4 + nt) * 32) + lane) * 4);
            D0[nt][0] = fmaf(ini.z, xg,  ini.x);
            D0[nt][1] = fmaf(ini.w, xg,  ini.y);
            D0[nt][2] = fmaf(ini.z, xg8, ini.x);
            D0[nt][3] = fmaf(ini.w, xg8, ini.y);
            float2 bi = *(const float2*)(si1 + (((w * 4 + nt) * 32) + lane) * 2);
            D1[nt][0] = bi.x; D1[nt][1] = bi.y;
            D1[nt][2] = bi.x; D1[nt][3] = bi.y;
        }

        // ---- GEMM0: D0 += Whh0 * h0(t-1)   (A = Af0) ----
#pragma unroll
        for (int kt = 0; kt < 8; kt++) {
            u32 a[4];
            *(uint4*)a = *(const uint4*)(Af0 + (kt * 32 + lane) * 4);
#pragma unroll
            for (int nt = 0; nt < 4; nt++)
                mma8(D0[nt], a, rh0[nt][kt][0], rh0[nt][kt][1]);
#pragma unroll
            for (int nt = 0; nt < 4; nt++) {
                u32 lp = lo0[FRAG(w, nt, kt, lane)];
                mma8(D0[nt], a, lp << 16, lp & 0xffff0000u);
            }
        }
        // ---- GEMM2: D1 += Whh1 * h1(t-1)   (A = Af1) ----
#pragma unroll
        for (int kt = 0; kt < 8; kt++) {
            u32 a[4];
            *(uint4*)a = *(const uint4*)(Af1 + (kt * 32 + lane) * 4);
#pragma unroll
            for (int nt = 0; nt < 4; nt++)
                mma8(D1[nt], a, rh2[nt][kt][0], rh2[nt][kt][1]);
#pragma unroll
            for (int nt = 0; nt < 4; nt++) {
                u32 lp = lo2[FRAG(w, nt, kt, lane)];
                mma8(D1[nt], a, lp << 16, lp & 0xffff0000u);
            }
        }

        // ---- cell 0 (warp-local; pair i,f with g,o via shfl_xor 1) ----
        float hv0[4];
#pragma unroll
        for (int nt = 0; nt < 4; nt++) {
            float s0 = evn ? D0[nt][2] : D0[nt][0];
            float s1 = evn ? D0[nt][3] : D0[nt][1];
            float r0 = __shfl_xor_sync(0xffffffffu, s0, 1);
            float r1 = __shfl_xor_sync(0xffffffffu, s1, 1);
            float iv = evn ? D0[nt][0] : r0;
            float fv = evn ? D0[nt][1] : r1;
            float gv = evn ? r0        : D0[nt][2];
            float ov = evn ? r1        : D0[nt][3];
            float cc = fmaf(sig_t(fv), c0[nt], sig_t(iv) * tanhax(gv));
            c0[nt] = cc;
            hv0[nt] = sig_t(ov) * tanhax(cc);
        }
        __syncthreads();                 // all reads of Af0/Af1 (t-1) done

        // publish h0(t) (tf32-rounded) into Af0
#pragma unroll
        for (int nt = 0; nt < 4; nt++)
            Af0[(w * 32 + lanep[nt]) * 4 + regn[nt]] = __uint_as_float(tf32r(hv0[nt]));
        __syncthreads();                 // Af0(t) visible

        // ---- GEMM1: D1 += Wih1 * h0(t)   (A = Af0 new) ----
#pragma unroll
        for (int kt = 0; kt < 8; kt++) {
            u32 a[4];
            *(uint4*)a = *(const uint4*)(Af0 + (kt * 32 + lane) * 4);
#pragma unroll
            for (int nt = 0; nt < 4; nt++) {
                uint2 hp = *(const uint2*)(w1h + FRAG(w, nt, kt, lane) * 2);
                mma8(D1[nt], a, hp.x, hp.y);
            }
#pragma unroll
            for (int nt = 0; nt < 4; nt++) {
                u32 lp = lo1[FRAG(w, nt, kt, lane)];
                mma8(D1[nt], a, lp << 16, lp & 0xffff0000u);
            }
        }

        // ---- cell 1 ----
#pragma unroll
        for (int nt = 0; nt < 4; nt++) {
            float s0 = evn ? D1[nt][2] : D1[nt][0];
            float s1 = evn ? D1[nt][3] : D1[nt][1];
            float r0 = __shfl_xor_sync(0xffffffffu, s0, 1);
            float r1 = __shfl_xor_sync(0xffffffffu, s1, 1);
            float iv = evn ? D1[nt][0] : r0;
            float fv = evn ? D1[nt][1] : r1;
            float gv = evn ? r0        : D1[nt][2];
            float ov = evn ? r1        : D1[nt][3];
            float cc = fmaf(sig_t(fv), c1[nt], sig_t(iv) * tanhax(gv));
            c1[nt] = cc;
            hv1[nt] = sig_t(ov) * tanhax(cc);
        }
        // publish h1(t) into Af1 (readers finished at first sync this step)
#pragma unroll
        for (int nt = 0; nt < 4; nt++)
            Af1[(w * 32 + lanep[nt]) * 4 + regn[nt]] = __uint_as_float(tf32r(hv1[nt]));
        __syncthreads();                 // Af1(t) visible for next step
    }

    // ---------------- epilogue ----------------
    // final h1 (full fp32, unrounded) -> hfin[b][u]
#pragma unroll
    for (int nt = 0; nt < 4; nt++)
        hfin[rr * 64 + (w * 8 + 2 * nt + uoff)] = hv1[nt];
    __syncthreads();

    for (int idx = tid; idx < 16 * OUTN; idx += NTHR) {
        int b = idx / OUTN, o = idx - b * OUTN;
        float s = fc_b[o];
#pragma unroll 16
        for (int uu = 0; uu < 64; uu++)
            s += hfin[b * 64 + uu] * fc_w[o * 64 + uu];
        out[(size_t)(b0g + b) * OUTN + o] = s;
    }
}

extern "C" void kernel_launch(void* const* d_in, const int* in_sizes, int n_in,
                              void* d_out, int out_size) {
    (void)in_sizes; (void)n_in; (void)out_size;
    const float* x     = (const float*)d_in[0];
    const float* w_ih0 = (const float*)d_in[1];
    const float* w_hh0 = (const float*)d_in[2];
    const float* b_ih0 = (const float*)d_in[3];
    const float* b_hh0 = (const float*)d_in[4];
    const float* w_ih1 = (const float*)d_in[5];
    const float* w_hh1 = (const float*)d_in[6];
    const float* b_ih1 = (const float*)d_in[7];
    const float* b_hh1 = (const float*)d_in[8];
    const float* fc_w  = (const float*)d_in[9];
    const float* fc_b  = (const float*)d_in[10];

    size_t smem = (size_t)SMEMF * sizeof(float);
    cudaFuncSetAttribute(lstm2_mma, cudaFuncAttributeMaxDynamicSharedMemorySize, (int)smem);
    lstm2_mma<<<CTAS, NTHR, smem>>>(x, w_ih0, w_hh0, b_ih0, b_hh0,
                                    w_ih1, w_hh1, b_ih1, b_hh1,
                                    fc_w, fc_b, (float*)d_out);
}

// round 10
// speedup vs baseline: 6.9627x; 1.3341x over previous
#include <cuda_runtime.h>
#include <cstdint>

#define SS   512
#define OUTN 12
#define CTAS 128
#define NTHR 256
#define XCH  64

typedef uint32_t u32;

__device__ __forceinline__ float tanhax(float x) {
    float r; asm("tanh.approx.f32 %0, %1;" : "=f"(r) : "f"(x)); return r;
}
__device__ __forceinline__ float sig_t(float x) { return fmaf(0.5f, tanhax(0.5f * x), 0.5f); }

__device__ __forceinline__ u32 bf16rn(float x) {      // f32 -> bf16 bits (RN)
    u32 u = __float_as_uint(x);
    u += 0x7fffu + ((u >> 16) & 1u);
    return u >> 16;
}
__device__ __forceinline__ u32 pkbf(float lo, float hi) {   // bf16x2: lo in low half
    return bf16rn(lo) | (bf16rn(hi) << 16);
}
__device__ __forceinline__ float bfres(float v) {     // residual after bf16 rounding
    return v - __uint_as_float(bf16rn(v) << 16);
}
// gate-interleaved column n = 4*u + g  ->  global weight row g*64 + u
__device__ __forceinline__ int grow(int n) { return (n & 3) * 64 + (n >> 2); }

__device__ __forceinline__ void mma16(float d[4], const u32 a[4], u32 b0, u32 b1) {
    asm volatile("mma.sync.aligned.m16n8k16.row.col.f32.bf16.bf16.f32 "
                 "{%0,%1,%2,%3}, {%4,%5,%6,%7}, {%8,%9}, {%0,%1,%2,%3};"
                 : "+f"(d[0]), "+f"(d[1]), "+f"(d[2]), "+f"(d[3])
                 : "r"(a[0]), "r"(a[1]), "r"(a[2]), "r"(a[3]), "r"(b0), "r"(b1));
}

// smem float offsets
#define OF_A0    0        // u32 A-frag buf layer0: [2 slot][4 kt][32 lane][4 reg]
#define OF_A1    1024
#define OF_XS    2048     // [XCH][16]
#define OF_HFIN  3072     // [16 b][64 u]
#define OF_SI0   4096     // [w][nt][lane][4]: bias0 n0, bias0 n1, wih0 n0, wih0 n1
#define OF_SI1   8192     // [w][nt][lane][2]: bias1 n0, bias1 n1
#define OF_W1H   10240    // Wih1 hi frag: [w][nt][kt][lane][2] u32
#define OF_L1    18432    // Wih1 lo frag, same shape
#define SMEMF    26624    // 104 KB

__global__ void __launch_bounds__(NTHR, 1) lstm2_bf16(
    const float* __restrict__ x,
    const float* __restrict__ w_ih0, const float* __restrict__ w_hh0,
    const float* __restrict__ b_ih0, const float* __restrict__ b_hh0,
    const float* __restrict__ w_ih1, const float* __restrict__ w_hh1,
    const float* __restrict__ b_ih1, const float* __restrict__ b_hh1,
    const float* __restrict__ fc_w, const float* __restrict__ fc_b,
    float* __restrict__ out)
{
    extern __shared__ float sm[];
    u32*   A0   = (u32*)(sm + OF_A0);
    u32*   A1   = (u32*)(sm + OF_A1);
    float* xs   = sm + OF_XS;
    float* hfin = sm + OF_HFIN;
    float* si0  = sm + OF_SI0;
    float* si1  = sm + OF_SI1;
    u32*   w1h  = (u32*)(sm + OF_W1H);
    u32*   l1f  = (u32*)(sm + OF_L1);

    const int tid  = threadIdx.x;
    const int lane = tid & 31;
    const int w    = tid >> 5;          // warp owns cols [32w, 32w+32)
    const int g    = lane >> 2;
    const int tg   = lane & 3;
    const int evn  = (tg & 1) == 0;
    const int rr   = g + 8 * (tg & 1);  // batch row this lane cells
    const int b0g  = blockIdx.x * 16;

    // ---------------- one-time staging ----------------
    for (int e = tid; e < 2048; e += NTHR) sm[e] = 0.f;   // zero A bufs (h(-1)=0)

    // weight fragments: hi+lo bf16. Whh0/Whh1 resident in regs; Wih1 in smem.
    u32 rh0[4][4][2], rl0[4][4][2], rh2[4][4][2], rl2[4][4][2];
    const int fb = (w * 512 + lane) * 2;   // per-warp frag base (u32 idx)
#pragma unroll
    for (int nt = 0; nt < 4; nt++) {
        const int n  = w * 32 + nt * 8 + g;
        const int gr = grow(n);
#pragma unroll
        for (int kt = 0; kt < 4; kt++) {
            const int k0 = 16 * kt + 2 * tg;
            // Whh0
            float v00 = w_hh0[gr * 64 + k0],     v01 = w_hh0[gr * 64 + k0 + 1];
            float v10 = w_hh0[gr * 64 + k0 + 8], v11 = w_hh0[gr * 64 + k0 + 9];
            rh0[nt][kt][0] = pkbf(v00, v01);
            rh0[nt][kt][1] = pkbf(v10, v11);
            rl0[nt][kt][0] = pkbf(bfres(v00), bfres(v01));
            rl0[nt][kt][1] = pkbf(bfres(v10), bfres(v11));
            // Whh1
            v00 = w_hh1[gr * 64 + k0];     v01 = w_hh1[gr * 64 + k0 + 1];
            v10 = w_hh1[gr * 64 + k0 + 8]; v11 = w_hh1[gr * 64 + k0 + 9];
            rh2[nt][kt][0] = pkbf(v00, v01);
            rh2[nt][kt][1] = pkbf(v10, v11);
            rl2[nt][kt][0] = pkbf(bfres(v00), bfres(v01));
            rl2[nt][kt][1] = pkbf(bfres(v10), bfres(v11));
            // Wih1 -> smem frags
            v00 = w_ih1[gr * 64 + k0];     v01 = w_ih1[gr * 64 + k0 + 1];
            v10 = w_ih1[gr * 64 + k0 + 8]; v11 = w_ih1[gr * 64 + k0 + 9];
            const int fo = fb + (nt * 4 + kt) * 64;
            w1h[fo + 0] = pkbf(v00, v01);
            w1h[fo + 1] = pkbf(v10, v11);
            l1f[fo + 0] = pkbf(bfres(v00), bfres(v01));
            l1f[fo + 1] = pkbf(bfres(v10), bfres(v11));
        }
        // bias / input-weight tables for this warp's cols (cols 2tg, 2tg+1 of ntile)
        const int n0 = w * 32 + nt * 8 + 2 * tg, n1 = n0 + 1;
        const int g0 = grow(n0), g1 = grow(n1);
        float* p0 = si0 + (((w * 4 + nt) * 32) + lane) * 4;
        p0[0] = b_ih0[g0] + b_hh0[g0];
        p0[1] = b_ih0[g1] + b_hh0[g1];
        p0[2] = w_ih0[g0];                 // INPUT_SIZE == 1
        p0[3] = w_ih0[g1];
        float* p1 = si1 + (((w * 4 + nt) * 32) + lane) * 2;
        p1[0] = b_ih1[g0] + b_hh1[g0];
        p1[1] = b_ih1[g1] + b_hh1[g1];
    }

    // publish slots: value (row rr, unit u = w*8 + 2nt + uoff) -> frag position
    int pub_idx[4];
#pragma unroll
    for (int nt = 0; nt < 4; nt++) {
        const int kpn = 4 * w + nt;          // unit-pair index in K
        const int kt_ = kpn >> 3, kp8 = kpn & 7;
        const int tgp = kp8 & 3;
        const int lane_ = (rr & 7) * 4 + tgp;
        const int reg = (kp8 >= 4 ? 2 : 0) + (rr >= 8 ? 1 : 0);
        pub_idx[nt] = (kt_ * 32 + lane_) * 4 + reg;
    }

    float c0[4] = {0.f, 0.f, 0.f, 0.f}, c1[4] = {0.f, 0.f, 0.f, 0.f};
    float hv1[4] = {0.f, 0.f, 0.f, 0.f};
    __syncthreads();

    // ---------------- recurrence ----------------
    for (int t = 0; t < SS; t++) {
        if ((t & (XCH - 1)) == 0) {          // refill x chunk [t, t+XCH)
            for (int e = tid; e < 16 * XCH; e += NTHR) {
                int tc = e & (XCH - 1), b = e >> 6;
                xs[tc * 16 + b] = x[(size_t)(b0g + b) * SS + t + tc];
            }
            __syncthreads();
        }
        const int p = t & 1;
        const u32* A0r = A0 + p * 512;
        const u32* A1r = A1 + p * 512;
        u32* A0w = A0 + (p ^ 1) * 512;
        u32* A1w = A1 + (p ^ 1) * 512;

        const int tloc = t & (XCH - 1);
        const float xg  = xs[tloc * 16 + g];
        const float xg8 = xs[tloc * 16 + g + 8];

        // ---- D0 = bias0 + wih0*x_t ;  D1 = bias1 ----
        float D0[4][4], D1[4][4];
#pragma unroll
        for (int nt = 0; nt < 4; nt++) {
            float4 ini = *(const float4*)(si0 + (((w * 4 + nt) * 32) + lane) * 4);
            D0[nt][0] = fmaf(ini.z, xg,  ini.x);
            D0[nt][1] = fmaf(ini.w, xg,  ini.y);
            D0[nt][2] = fmaf(ini.z, xg8, ini.x);
            D0[nt][3] = fmaf(ini.w, xg8, ini.y);
            float2 bi = *(const float2*)(si1 + (((w * 4 + nt) * 32) + lane) * 2);
            D1[nt][0] = bi.x; D1[nt][1] = bi.y;
            D1[nt][2] = bi.x; D1[nt][3] = bi.y;
        }

        // ---- GEMM0 (D0 += Whh0*h0) and GEMM2 (D1 += Whh1*h1), interleaved ----
#pragma unroll
        for (int kt = 0; kt < 4; kt++) {
            u32 a[4], b[4];
            *(uint4*)a = *(const uint4*)(A0r + (kt * 32 + lane) * 4);
            *(uint4*)b = *(const uint4*)(A1r + (kt * 32 + lane) * 4);
#pragma unroll
            for (int nt = 0; nt < 4; nt++) {
                mma16(D0[nt], a, rh0[nt][kt][0], rh0[nt][kt][1]);
                mma16(D1[nt], b, rh2[nt][kt][0], rh2[nt][kt][1]);
                mma16(D0[nt], a, rl0[nt][kt][0], rl0[nt][kt][1]);
                mma16(D1[nt], b, rl2[nt][kt][0], rl2[nt][kt][1]);
            }
        }

        // ---- cell 0 (warp-local; pair i,f with g,o via shfl_xor 1) ----
        float hv0[4];
#pragma unroll
        for (int nt = 0; nt < 4; nt++) {
            float s0 = evn ? D0[nt][2] : D0[nt][0];
            float s1 = evn ? D0[nt][3] : D0[nt][1];
            float r0 = __shfl_xor_sync(0xffffffffu, s0, 1);
            float r1 = __shfl_xor_sync(0xffffffffu, s1, 1);
            float iv = evn ? D0[nt][0] : r0;
            float fv = evn ? D0[nt][1] : r1;
            float gv = evn ? r0        : D0[nt][2];
            float ov = evn ? r1        : D0[nt][3];
            float cc = fmaf(sig_t(fv), c0[nt], sig_t(iv) * tanhax(gv));
            c0[nt] = cc;
            hv0[nt] = sig_t(ov) * tanhax(cc);
        }
        // publish h0(t) as bf16x2 into alternate buffer (pair units via shfl_xor 2)
#pragma unroll
        for (int nt = 0; nt < 4; nt++) {
            float oth = __shfl_xor_sync(0xffffffffu, hv0[nt], 2);
            if (tg < 2) A0w[pub_idx[nt]] = pkbf(hv0[nt], oth);
        }
        __syncthreads();                     // A: h0(t) visible

        // ---- GEMM1: D1 += Wih1 * h0(t) ----
#pragma unroll
        for (int kt = 0; kt < 4; kt++) {
            u32 a[4];
            *(uint4*)a = *(const uint4*)(A0w + (kt * 32 + lane) * 4);
#pragma unroll
            for (int nt = 0; nt < 4; nt++) {
                uint2 hp = *(const uint2*)(w1h + fb + (nt * 4 + kt) * 64);
                mma16(D1[nt], a, hp.x, hp.y);
                uint2 lp = *(const uint2*)(l1f + fb + (nt * 4 + kt) * 64);
                mma16(D1[nt], a, lp.x, lp.y);
            }
        }

        // ---- cell 1 ----
#pragma unroll
        for (int nt = 0; nt < 4; nt++) {
            float s0 = evn ? D1[nt][2] : D1[nt][0];
            float s1 = evn ? D1[nt][3] : D1[nt][1];
            float r0 = __shfl_xor_sync(0xffffffffu, s0, 1);
            float r1 = __shfl_xor_sync(0xffffffffu, s1, 1);
            float iv = evn ? D1[nt][0] : r0;
            float fv = evn ? D1[nt][1] : r1;
            float gv = evn ? r0        : D1[nt][2];
            float ov = evn ? r1        : D1[nt][3];
            float cc = fmaf(sig_t(fv), c1[nt], sig_t(iv) * tanhax(gv));
            c1[nt] = cc;
            hv1[nt] = sig_t(ov) * tanhax(cc);
        }
#pragma unroll
        for (int nt = 0; nt < 4; nt++) {
            float oth = __shfl_xor_sync(0xffffffffu, hv1[nt], 2);
            if (tg < 2) A1w[pub_idx[nt]] = pkbf(hv1[nt], oth);
        }
        __syncthreads();                     // B: h1(t) visible for next step
    }

    // ---------------- epilogue ----------------
#pragma unroll
    for (int nt = 0; nt < 4; nt++)
        hfin[rr * 64 + (w * 8 + 2 * nt + (tg >> 1))] = hv1[nt];
    __syncthreads();

    for (int idx = tid; idx < 16 * OUTN; idx += NTHR) {
        int b = idx / OUTN, o = idx - b * OUTN;
        float s = fc_b[o];
#pragma unroll 16
        for (int uu = 0; uu < 64; uu++)
            s += hfin[b * 64 + uu] * fc_w[o * 64 + uu];
        out[(size_t)(b0g + b) * OUTN + o] = s;
    }
}

extern "C" void kernel_launch(void* const* d_in, const int* in_sizes, int n_in,
                              void* d_out, int out_size) {
    (void)in_sizes; (void)n_in; (void)out_size;
    const float* x     = (const float*)d_in[0];
    const float* w_ih0 = (const float*)d_in[1];
    const float* w_hh0 = (const float*)d_in[2];
    const float* b_ih0 = (const float*)d_in[3];
    const float* b_hh0 = (const float*)d_in[4];
    const float* w_ih1 = (const float*)d_in[5];
    const float* w_hh1 = (const float*)d_in[6];
    const float* b_ih1 = (const float*)d_in[7];
    const float* b_hh1 = (const float*)d_in[8];
    const float* fc_w  = (const float*)d_in[9];
    const float* fc_b  = (const float*)d_in[10];

    size_t smem = (size_t)SMEMF * sizeof(float);
    cudaFuncSetAttribute(lstm2_bf16, cudaFuncAttributeMaxDynamicSharedMemorySize, (int)smem);
    lstm2_bf16<<<CTAS, NTHR, smem>>>(x, w_ih0, w_hh0, b_ih0, b_hh0,
                                     w_ih1, w_hh1, b_ih1, b_hh1,
                                     fc_w, fc_b, (float*)d_out);
}